// round 11
// baseline (speedup 1.0000x reference)
#include <cuda_runtime.h>
#include <cuda_fp16.h>
#include <math.h>
#include <stdint.h>
#include <mma.h>

using namespace nvcuda;

// ===================== static scratch (no allocs allowed) ====================
__device__ __half g_q[2048 * 2048];    // Q projection (fp16)
__device__ __half g_y[2048 * 2048];    // attention out (fp16)
__device__ __half g_k[512 * 512];      // kproj fp16
__device__ __half g_v[512 * 512];      // vproj fp16
__device__ __half g_hx[2048 * 2048];   // x   in fp16
__device__ __half g_hcst[512 * 2048];  // cst in fp16
__device__ __half g_hwq[2048 * 2048];
__device__ __half g_hwk[2048 * 512];
__device__ __half g_hwv[2048 * 512];
__device__ __half g_hwo[2048 * 2048];

__device__ __forceinline__ uint32_t smem_u32(const void* p) {
    uint32_t a;
    asm("{ .reg .u64 t; cvta.to.shared.u64 t, %1; cvt.u32.u64 %0, t; }"
        : "=r"(a) : "l"(p));
    return a;
}
__device__ __forceinline__ void cp_async16(uint32_t dst, const void* src) {
    asm volatile("cp.async.cg.shared.global [%0], [%1], 16;" :: "r"(dst), "l"(src));
}
__device__ __forceinline__ void cp_commit() {
    asm volatile("cp.async.commit_group;" ::: "memory");
}
template <int N>
__device__ __forceinline__ void cp_wait() {
    asm volatile("cp.async.wait_group %0;" :: "n"(N) : "memory");
}

// ===================== fp32 -> fp16 conversion (grid-stride) ================
__global__ void __launch_bounds__(256)
cvt_all(const float* __restrict__ x, const float* __restrict__ cst,
        const float* __restrict__ wq, const float* __restrict__ wk,
        const float* __restrict__ wv, const float* __restrict__ wo,
        __half* __restrict__ hx, __half* __restrict__ hcst,
        __half* __restrict__ hwq, __half* __restrict__ hwk,
        __half* __restrict__ hwv, __half* __restrict__ hwo) {
    for (size_t i4 = (size_t)blockIdx.x * 256 + threadIdx.x; i4 < 3932160u;
         i4 += (size_t)gridDim.x * 256) {
        size_t i = i4 * 4;
        const float* src; __half* dst; size_t off;
        if      (i <  4194304u) { src = x;   dst = hx;   off = i; }
        else if (i <  5242880u) { src = cst; dst = hcst; off = i - 4194304u; }
        else if (i <  9437184u) { src = wq;  dst = hwq;  off = i - 5242880u; }
        else if (i < 10485760u) { src = wk;  dst = hwk;  off = i - 9437184u; }
        else if (i < 11534336u) { src = wv;  dst = hwv;  off = i - 10485760u; }
        else                    { src = wo;  dst = hwo;  off = i - 11534336u; }
        float4 v = *(const float4*)(src + off);
        *(__half2*)(dst + off)     = __floats2half2_rn(v.x, v.y);
        *(__half2*)(dst + off + 2) = __floats2half2_rn(v.z, v.w);
    }
}

// ===================== fp16 cp.async GEMM ===================================
// C[M,N] = A[M,K](fp16) @ B[K,N](fp16). BM=BN=128, BK=64, 256 threads
// (8 warps as 4x2, warp tile 32x64), 3-stage cp.async pipeline, 2 CTAs/SM.
// EPI: 1 = fp32 out * tanh(gate), 2 = fp16 out (smem-staged).
constexpr int BK = 64, STAGES = 3;
constexpr int LDA = 72;    // halves (64 + 8 pad) -> 144B pitch
constexpr int LDB = 136;   // halves (128 + 8 pad) -> 272B pitch
constexpr int A_BYTES = 128 * LDA * 2;           // 18432
constexpr int B_BYTES = BK * LDB * 2;            // 17408
constexpr int STAGE_BYTES = A_BYTES + B_BYTES;   // 35840
constexpr int GEMM_SMEM = STAGES * STAGE_BYTES;  // 107520

template <int EPI, typename OutT>
__device__ __forceinline__ void gemm_body(
    const __half* __restrict__ A, const __half* __restrict__ B,
    OutT* __restrict__ C, int N, int K,
    const float* __restrict__ gate, int bx, int by, char* smem) {
    const uint32_t sb = smem_u32(smem);
    const int tid = threadIdx.x;
    const int wid = tid >> 5;
    const int lane = tid & 31;
    const int wm0 = (wid >> 1) * 32;
    const int wn0 = (wid & 1) * 64;
    const int row0 = by * 128;
    const int col0 = bx * 128;
    const int NIT = K / BK;

    const int a_r0 = tid >> 3, a_qb = (tid & 7) * 16;
    const int b_r0 = tid >> 4, b_qb = (tid & 15) * 16;

    auto issue = [&](int it) {
        const int s = it % STAGES;
        const int k0 = it * BK;
        const uint32_t As = sb + s * STAGE_BYTES;
        const uint32_t Bs = As + A_BYTES;
#pragma unroll
        for (int p = 0; p < 4; p++) {
            int r = a_r0 + p * 32;
            cp_async16(As + r * 144 + a_qb,
                       A + (size_t)(row0 + r) * K + k0 + (a_qb >> 1));
        }
#pragma unroll
        for (int p = 0; p < 4; p++) {
            int r = b_r0 + p * 16;
            cp_async16(Bs + r * 272 + b_qb,
                       B + (size_t)(k0 + r) * N + col0 + (b_qb >> 1));
        }
    };

    wmma::fragment<wmma::accumulator, 16, 16, 16, float> acc[2][4];
#pragma unroll
    for (int i = 0; i < 2; i++)
#pragma unroll
        for (int j = 0; j < 4; j++) wmma::fill_fragment(acc[i][j], 0.0f);

#pragma unroll
    for (int s = 0; s < STAGES - 1; s++) {
        issue(s);
        cp_commit();
    }

    for (int it = 0; it < NIT; ++it) {
        cp_wait<STAGES - 2>();
        __syncthreads();

        const int s = it % STAGES;
        const __half* Ah = (const __half*)(smem + s * STAGE_BYTES);
        const __half* Bh = (const __half*)(smem + s * STAGE_BYTES + A_BYTES);

#pragma unroll
        for (int ks = 0; ks < BK / 16; ks++) {
            wmma::fragment<wmma::matrix_a, 16, 16, 16, __half, wmma::row_major> af[2];
            wmma::fragment<wmma::matrix_b, 16, 16, 16, __half, wmma::row_major> bf[4];
#pragma unroll
            for (int i = 0; i < 2; i++)
                wmma::load_matrix_sync(af[i], Ah + (wm0 + i * 16) * LDA + ks * 16, LDA);
#pragma unroll
            for (int j = 0; j < 4; j++)
                wmma::load_matrix_sync(bf[j], Bh + (ks * 16) * LDB + wn0 + j * 16, LDB);
#pragma unroll
            for (int i = 0; i < 2; i++)
#pragma unroll
                for (int j = 0; j < 4; j++)
                    wmma::mma_sync(acc[i][j], af[i], bf[j], acc[i][j]);
        }

        if (it + STAGES - 1 < NIT) issue(it + STAGES - 1);
        cp_commit();
    }

    if (EPI == 2) {
        __syncthreads();
        float* scratch = (float*)smem + wid * 256;
        __half* Ch = (__half*)C;
        const int r = lane >> 1, c8 = (lane & 1) * 8;
#pragma unroll
        for (int i = 0; i < 2; i++)
#pragma unroll
            for (int j = 0; j < 4; j++) {
                wmma::store_matrix_sync(scratch, acc[i][j], 16, wmma::mem_row_major);
                __syncwarp();
                float4 v0 = *(float4*)(scratch + r * 16 + c8);
                float4 v1 = *(float4*)(scratch + r * 16 + c8 + 4);
                __half2 h[4];
                h[0] = __floats2half2_rn(v0.x, v0.y);
                h[1] = __floats2half2_rn(v0.z, v0.w);
                h[2] = __floats2half2_rn(v1.x, v1.y);
                h[3] = __floats2half2_rn(v1.z, v1.w);
                *(uint4*)(Ch + (size_t)(row0 + wm0 + i * 16 + r) * N +
                          col0 + wn0 + j * 16 + c8) = *(uint4*)h;
                __syncwarp();
            }
    } else {
        float g = tanhf(gate[0]);
        float* Cf = (float*)C;
#pragma unroll
        for (int i = 0; i < 2; i++)
#pragma unroll
            for (int j = 0; j < 4; j++) {
#pragma unroll
                for (int e = 0; e < acc[i][j].num_elements; e++)
                    acc[i][j].x[e] *= g;
                wmma::store_matrix_sync(
                    Cf + (size_t)(row0 + wm0 + i * 16) * N + col0 + wn0 + j * 16,
                    acc[i][j], N, wmma::mem_row_major);
            }
    }
}

// stage 1: fused Q(fp16) + kproj(fp16) + vproj(fp16). 288 CTAs, 2/SM.
__global__ void __launch_bounds__(256, 2)
fused_gemm1(const __half* __restrict__ hx, const __half* __restrict__ hcst,
            const __half* __restrict__ hwq, const __half* __restrict__ hwk,
            const __half* __restrict__ hwv, __half* __restrict__ qb,
            __half* __restrict__ kb, __half* __restrict__ vb) {
    extern __shared__ char smem[];
    int bid = blockIdx.x;
    if (bid < 256) {
        gemm_body<2, __half>(hx, hwq, qb, 2048, 2048, nullptr, bid & 15, bid >> 4, smem);
    } else {
        int t = bid - 256;
        int w = t >> 4;
        t &= 15;
        gemm_body<2, __half>(hcst, w ? hwv : hwk, w ? vb : kb, 512, 2048,
                             nullptr, t & 3, t >> 2, smem);
    }
}

// stage 4: out = (y @ Wo) * tanh(gate). 256 CTAs, 2/SM.
__global__ void __launch_bounds__(256, 2)
out_gemm(const __half* __restrict__ y, const __half* __restrict__ hwo,
         float* __restrict__ out, const float* __restrict__ gate) {
    extern __shared__ char smem[];
    gemm_body<1, float>(y, hwo, out, 2048, 2048, gate, blockIdx.x & 15,
                        blockIdx.x >> 4, smem);
}

// ===================== tiny-K attention =====================================
// Block = (token bt, kv-group g), 4 warps = 4 rep heads, lane = key.
// fp16 gmem traffic; convert ONCE to fp32 at smem staging; pure float4
// LDS+FFMA inner loops (numerics identical to converting at use).
__global__ void __launch_bounds__(128)
attn_kernel(const __half* __restrict__ qh, const __half* __restrict__ kh,
            const __half* __restrict__ vh, const int* __restrict__ mask,
            __half* __restrict__ y) {
    __shared__ float4 qsf[4][32];    // 2 KB   (head-major, broadcast reads)
    __shared__ float4 ksf[32][33];   // 16.9 KB (row = key, pitch 33 -> no conflicts)
    __shared__ float4 vsf[32][33];   // 16.9 KB

    const int bt = blockIdx.x;
    const int g  = blockIdx.y;
    const int b  = bt >> 10;
    const int tid  = threadIdx.x;
    const int lane = tid & 31;
    const int w    = tid >> 5;

    const int ch = mask[bt];
    const size_t kvbase = ((size_t)(b * 8 + ch) * 32) * 512 + g * 128;

    // q: 512 halves -> 128 float4 (1 per thread)
    {
        uint2 qr = *(const uint2*)(qh + (size_t)bt * 2048 + g * 512 + tid * 4);
        float2 f0 = __half22float2(*(const __half2*)&qr.x);
        float2 f1 = __half22float2(*(const __half2*)&qr.y);
        qsf[tid >> 5][tid & 31] = make_float4(f0.x, f0.y, f1.x, f1.y);
    }
    // K, V: 32 rows x 32 float4 each (8 per thread per array)
#pragma unroll
    for (int p = 0; p < 8; p++) {
        int i = tid + p * 128;
        int r = i >> 5, c = i & 31;
        uint2 kr = *(const uint2*)(kh + kvbase + (size_t)r * 512 + c * 4);
        uint2 vr = *(const uint2*)(vh + kvbase + (size_t)r * 512 + c * 4);
        float2 k0 = __half22float2(*(const __half2*)&kr.x);
        float2 k1 = __half22float2(*(const __half2*)&kr.y);
        float2 v0 = __half22float2(*(const __half2*)&vr.x);
        float2 v1 = __half22float2(*(const __half2*)&vr.y);
        ksf[r][c] = make_float4(k0.x, k0.y, k1.x, k1.y);
        vsf[r][c] = make_float4(v0.x, v0.y, v1.x, v1.y);
    }
    __syncthreads();

    // score: lane = key, warp = head; pure float4 FMA
    float sc = 0.0f;
#pragma unroll
    for (int c = 0; c < 32; c++) {
        float4 qa = qsf[w][c];       // broadcast
        float4 ka = ksf[lane][c];
        sc += qa.x * ka.x + qa.y * ka.y + qa.z * ka.z + qa.w * ka.w;
    }
    sc *= 0.08838834764831845f;  // 1/sqrt(128)

    float m = sc;
#pragma unroll
    for (int off = 16; off; off >>= 1) m = fmaxf(m, __shfl_xor_sync(0xFFFFFFFFu, m, off));
    float e = __expf(sc - m);
    float s = e;
#pragma unroll
    for (int off = 16; off; off >>= 1) s += __shfl_xor_sync(0xFFFFFFFFu, s, off);
    const float wat = e / s;

    // AV: lane owns 4 dims
    float4 acc = make_float4(0.f, 0.f, 0.f, 0.f);
#pragma unroll
    for (int kk = 0; kk < 32; kk++) {
        float a = __shfl_sync(0xFFFFFFFFu, wat, kk);
        float4 v4 = vsf[kk][lane];
        acc.x += a * v4.x; acc.y += a * v4.y;
        acc.z += a * v4.z; acc.w += a * v4.w;
    }
    __half2 h0 = __floats2half2_rn(acc.x, acc.y);
    __half2 h1 = __floats2half2_rn(acc.z, acc.w);
    uint32_t u0, u1;
    memcpy(&u0, &h0, 4);
    memcpy(&u1, &h1, 4);
    *(uint2*)(y + (size_t)bt * 2048 + g * 512 + w * 128 + lane * 4) =
        make_uint2(u0, u1);
}

// ===================== launch ===============================================
extern "C" void kernel_launch(void* const* d_in, const int* in_sizes, int n_in,
                              void* d_out, int out_size) {
    const float* x    = (const float*)d_in[0];
    const float* cst  = (const float*)d_in[1];
    const int*   mask = (const int*)d_in[2];
    const float* Wq   = (const float*)d_in[3];
    const float* Wk   = (const float*)d_in[4];
    const float* Wv   = (const float*)d_in[5];
    const float* Wo   = (const float*)d_in[6];
    const float* gate = (const float*)d_in[7];
    float* out = (float*)d_out;

    __half *qb, *kb, *vb, *yb, *hx, *hcst, *hwq, *hwk, *hwv, *hwo;
    cudaGetSymbolAddress((void**)&qb, g_q);
    cudaGetSymbolAddress((void**)&yb, g_y);
    cudaGetSymbolAddress((void**)&kb, g_k);
    cudaGetSymbolAddress((void**)&vb, g_v);
    cudaGetSymbolAddress((void**)&hx, g_hx);
    cudaGetSymbolAddress((void**)&hcst, g_hcst);
    cudaGetSymbolAddress((void**)&hwq, g_hwq);
    cudaGetSymbolAddress((void**)&hwk, g_hwk);
    cudaGetSymbolAddress((void**)&hwv, g_hwv);
    cudaGetSymbolAddress((void**)&hwo, g_hwo);

    cudaFuncSetAttribute(fused_gemm1,
                         cudaFuncAttributeMaxDynamicSharedMemorySize, GEMM_SMEM);
    cudaFuncSetAttribute(out_gemm,
                         cudaFuncAttributeMaxDynamicSharedMemorySize, GEMM_SMEM);

    // 0) convert all GEMM inputs to fp16 (grid-stride)
    cvt_all<<<1480, 256>>>(x, cst, Wq, Wk, Wv, Wo, hx, hcst, hwq, hwk, hwv, hwo);
    // 1+2) Q + kproj + vproj, all fp16 outputs
    fused_gemm1<<<288, 256, GEMM_SMEM>>>(hx, hcst, hwq, hwk, hwv, qb, kb, vb);
    // 3) gather + tiny-K GQA attention (fp32 math in smem)
    attn_kernel<<<dim3(2048, 4), 128>>>(qb, kb, vb, mask, yb);
    // 4) out = (y @ Wo) * tanh(gate)
    out_gemm<<<256, 256, GEMM_SMEM>>>(yb, hwo, out, gate);
}

// round 12
// speedup vs baseline: 1.0269x; 1.0269x over previous
#include <cuda_runtime.h>
#include <cuda_fp16.h>
#include <math.h>
#include <stdint.h>
#include <mma.h>

using namespace nvcuda;

// ===================== static scratch (no allocs allowed) ====================
__device__ __half g_q[2048 * 2048];    // Q projection (fp16)
__device__ __half g_y[2048 * 2048];    // attention out (fp16)
__device__ __half g_k[512 * 512];      // kproj fp16
__device__ __half g_v[512 * 512];      // vproj fp16
__device__ __half g_hx[2048 * 2048];   // x   in fp16
__device__ __half g_hcst[512 * 2048];  // cst in fp16
__device__ __half g_hwq[2048 * 2048];
__device__ __half g_hwk[2048 * 512];
__device__ __half g_hwv[2048 * 512];
__device__ __half g_hwo[2048 * 2048];

__device__ __forceinline__ uint32_t smem_u32(const void* p) {
    uint32_t a;
    asm("{ .reg .u64 t; cvta.to.shared.u64 t, %1; cvt.u32.u64 %0, t; }"
        : "=r"(a) : "l"(p));
    return a;
}
__device__ __forceinline__ void cp_async16(uint32_t dst, const void* src) {
    asm volatile("cp.async.cg.shared.global [%0], [%1], 16;" :: "r"(dst), "l"(src));
}
__device__ __forceinline__ void cp_commit() {
    asm volatile("cp.async.commit_group;" ::: "memory");
}
template <int N>
__device__ __forceinline__ void cp_wait() {
    asm volatile("cp.async.wait_group %0;" :: "n"(N) : "memory");
}

// ===================== fp32 -> fp16 conversion (one-shot, as R9) ============
__global__ void __launch_bounds__(256)
cvt_all(const float* __restrict__ x, const float* __restrict__ cst,
        const float* __restrict__ wq, const float* __restrict__ wk,
        const float* __restrict__ wv, const float* __restrict__ wo,
        __half* __restrict__ hx, __half* __restrict__ hcst,
        __half* __restrict__ hwq, __half* __restrict__ hwk,
        __half* __restrict__ hwv, __half* __restrict__ hwo) {
    size_t i = ((size_t)blockIdx.x * blockDim.x + threadIdx.x) * 4;
    const float* src; __half* dst; size_t off;
    if      (i <  4194304u) { src = x;   dst = hx;   off = i; }
    else if (i <  5242880u) { src = cst; dst = hcst; off = i - 4194304u; }
    else if (i <  9437184u) { src = wq;  dst = hwq;  off = i - 5242880u; }
    else if (i < 10485760u) { src = wk;  dst = hwk;  off = i - 9437184u; }
    else if (i < 11534336u) { src = wv;  dst = hwv;  off = i - 10485760u; }
    else if (i < 15728640u) { src = wo;  dst = hwo;  off = i - 11534336u; }
    else return;
    float4 v = *(const float4*)(src + off);
    *(__half2*)(dst + off)     = __floats2half2_rn(v.x, v.y);
    *(__half2*)(dst + off + 2) = __floats2half2_rn(v.z, v.w);
}

// ===================== fp16 cp.async GEMM ===================================
// C[M,N] = A[M,K](fp16) @ B[K,N](fp16). BM=BN=128, BK=64, 256 threads
// (8 warps as 4x2, warp tile 32x64), 3-stage cp.async pipeline, 2 CTAs/SM.
// EPI: 1 = fp32 out * tanh(gate), 2 = fp16 out (smem-staged).
constexpr int BK = 64, STAGES = 3;
constexpr int LDA = 72;    // halves (64 + 8 pad) -> 144B pitch
constexpr int LDB = 136;   // halves (128 + 8 pad) -> 272B pitch
constexpr int A_BYTES = 128 * LDA * 2;           // 18432
constexpr int B_BYTES = BK * LDB * 2;            // 17408
constexpr int STAGE_BYTES = A_BYTES + B_BYTES;   // 35840
constexpr int GEMM_SMEM = STAGES * STAGE_BYTES;  // 107520

template <int EPI, typename OutT>
__device__ __forceinline__ void gemm_body(
    const __half* __restrict__ A, const __half* __restrict__ B,
    OutT* __restrict__ C, int N, int K,
    const float* __restrict__ gate, int bx, int by, char* smem) {
    const uint32_t sb = smem_u32(smem);
    const int tid = threadIdx.x;
    const int wid = tid >> 5;
    const int lane = tid & 31;
    const int wm0 = (wid >> 1) * 32;
    const int wn0 = (wid & 1) * 64;
    const int row0 = by * 128;
    const int col0 = bx * 128;
    const int NIT = K / BK;

    const int a_r0 = tid >> 3, a_qb = (tid & 7) * 16;
    const int b_r0 = tid >> 4, b_qb = (tid & 15) * 16;

    auto issue = [&](int it) {
        const int s = it % STAGES;
        const int k0 = it * BK;
        const uint32_t As = sb + s * STAGE_BYTES;
        const uint32_t Bs = As + A_BYTES;
#pragma unroll
        for (int p = 0; p < 4; p++) {
            int r = a_r0 + p * 32;
            cp_async16(As + r * 144 + a_qb,
                       A + (size_t)(row0 + r) * K + k0 + (a_qb >> 1));
        }
#pragma unroll
        for (int p = 0; p < 4; p++) {
            int r = b_r0 + p * 16;
            cp_async16(Bs + r * 272 + b_qb,
                       B + (size_t)(k0 + r) * N + col0 + (b_qb >> 1));
        }
    };

    wmma::fragment<wmma::accumulator, 16, 16, 16, float> acc[2][4];
#pragma unroll
    for (int i = 0; i < 2; i++)
#pragma unroll
        for (int j = 0; j < 4; j++) wmma::fill_fragment(acc[i][j], 0.0f);

#pragma unroll
    for (int s = 0; s < STAGES - 1; s++) {
        issue(s);
        cp_commit();
    }

    for (int it = 0; it < NIT; ++it) {
        cp_wait<STAGES - 2>();
        __syncthreads();

        // EARLY ISSUE: stage (it+2)%3 == (it-1)%3 was fully consumed in iter
        // it-1 (barrier above proves all warps are past it). Issuing before
        // the MMA block gives the loads the whole compute window to land.
        if (it + STAGES - 1 < NIT) issue(it + STAGES - 1);
        cp_commit();

        const int s = it % STAGES;
        const __half* Ah = (const __half*)(smem + s * STAGE_BYTES);
        const __half* Bh = (const __half*)(smem + s * STAGE_BYTES + A_BYTES);

#pragma unroll
        for (int ks = 0; ks < BK / 16; ks++) {
            wmma::fragment<wmma::matrix_a, 16, 16, 16, __half, wmma::row_major> af[2];
            wmma::fragment<wmma::matrix_b, 16, 16, 16, __half, wmma::row_major> bf[4];
#pragma unroll
            for (int i = 0; i < 2; i++)
                wmma::load_matrix_sync(af[i], Ah + (wm0 + i * 16) * LDA + ks * 16, LDA);
#pragma unroll
            for (int j = 0; j < 4; j++)
                wmma::load_matrix_sync(bf[j], Bh + (ks * 16) * LDB + wn0 + j * 16, LDB);
#pragma unroll
            for (int i = 0; i < 2; i++)
#pragma unroll
                for (int j = 0; j < 4; j++)
                    wmma::mma_sync(acc[i][j], af[i], bf[j], acc[i][j]);
        }
    }

    if (EPI == 2) {
        __syncthreads();
        float* scratch = (float*)smem + wid * 256;
        __half* Ch = (__half*)C;
        const int r = lane >> 1, c8 = (lane & 1) * 8;
#pragma unroll
        for (int i = 0; i < 2; i++)
#pragma unroll
            for (int j = 0; j < 4; j++) {
                wmma::store_matrix_sync(scratch, acc[i][j], 16, wmma::mem_row_major);
                __syncwarp();
                float4 v0 = *(float4*)(scratch + r * 16 + c8);
                float4 v1 = *(float4*)(scratch + r * 16 + c8 + 4);
                __half2 h[4];
                h[0] = __floats2half2_rn(v0.x, v0.y);
                h[1] = __floats2half2_rn(v0.z, v0.w);
                h[2] = __floats2half2_rn(v1.x, v1.y);
                h[3] = __floats2half2_rn(v1.z, v1.w);
                *(uint4*)(Ch + (size_t)(row0 + wm0 + i * 16 + r) * N +
                          col0 + wn0 + j * 16 + c8) = *(uint4*)h;
                __syncwarp();
            }
    } else {
        float g = tanhf(gate[0]);
        float* Cf = (float*)C;
#pragma unroll
        for (int i = 0; i < 2; i++)
#pragma unroll
            for (int j = 0; j < 4; j++) {
#pragma unroll
                for (int e = 0; e < acc[i][j].num_elements; e++)
                    acc[i][j].x[e] *= g;
                wmma::store_matrix_sync(
                    Cf + (size_t)(row0 + wm0 + i * 16) * N + col0 + wn0 + j * 16,
                    acc[i][j], N, wmma::mem_row_major);
            }
    }
}

// stage 1: fused Q(fp16) + kproj(fp16) + vproj(fp16). 288 CTAs, 2/SM.
__global__ void __launch_bounds__(256, 2)
fused_gemm1(const __half* __restrict__ hx, const __half* __restrict__ hcst,
            const __half* __restrict__ hwq, const __half* __restrict__ hwk,
            const __half* __restrict__ hwv, __half* __restrict__ qb,
            __half* __restrict__ kb, __half* __restrict__ vb) {
    extern __shared__ char smem[];
    int bid = blockIdx.x;
    if (bid < 256) {
        gemm_body<2, __half>(hx, hwq, qb, 2048, 2048, nullptr, bid & 15, bid >> 4, smem);
    } else {
        int t = bid - 256;
        int w = t >> 4;
        t &= 15;
        gemm_body<2, __half>(hcst, w ? hwv : hwk, w ? vb : kb, 512, 2048,
                             nullptr, t & 3, t >> 2, smem);
    }
}

// stage 4: out = (y @ Wo) * tanh(gate). 256 CTAs, 2/SM.
__global__ void __launch_bounds__(256, 2)
out_gemm(const __half* __restrict__ y, const __half* __restrict__ hwo,
         float* __restrict__ out, const float* __restrict__ gate) {
    extern __shared__ char smem[];
    gemm_body<1, float>(y, hwo, out, 2048, 2048, gate, blockIdx.x & 15,
                        blockIdx.x >> 4, smem);
}

// ===================== tiny-K attention (R9 version, fp16 smem) =============
__global__ void __launch_bounds__(128)
attn_kernel(const __half* __restrict__ qh, const __half* __restrict__ kh,
            const __half* __restrict__ vh, const int* __restrict__ mask,
            __half* __restrict__ y) {
    __shared__ uint4 qsh[4][17];     // 4 heads x 128 halves (+pad)
    __shared__ uint4 ksh[32][17];    // 32 keys x 128 halves (+pad)
    __shared__ uint4 vsh[32][17];

    const int bt = blockIdx.x;
    const int g  = blockIdx.y;
    const int b  = bt >> 10;
    const int tid  = threadIdx.x;
    const int lane = tid & 31;
    const int w    = tid >> 5;

    const int ch = mask[bt];
    const size_t kvbase = ((size_t)(b * 8 + ch) * 32) * 512 + g * 128;

    if (tid < 64)
        qsh[tid >> 4][tid & 15] =
            *(const uint4*)(qh + (size_t)bt * 2048 + g * 512 + tid * 8);
#pragma unroll
    for (int p = 0; p < 4; p++) {
        int i = tid + p * 128;
        ksh[i >> 4][i & 15] =
            *(const uint4*)(kh + kvbase + (size_t)(i >> 4) * 512 + (i & 15) * 8);
        vsh[i >> 4][i & 15] =
            *(const uint4*)(vh + kvbase + (size_t)(i >> 4) * 512 + (i & 15) * 8);
    }
    __syncthreads();

    float sc = 0.0f;
#pragma unroll
    for (int c = 0; c < 16; c++) {
        uint4 k4 = qsh[w][c];       // broadcast
        uint4 kk4 = ksh[lane][c];
        const __half2* qp = (const __half2*)&k4;
        const __half2* kp = (const __half2*)&kk4;
#pragma unroll
        for (int u = 0; u < 4; u++) {
            float2 qf = __half22float2(qp[u]);
            float2 kf = __half22float2(kp[u]);
            sc += qf.x * kf.x + qf.y * kf.y;
        }
    }
    sc *= 0.08838834764831845f;  // 1/sqrt(128)

    float m = sc;
#pragma unroll
    for (int off = 16; off; off >>= 1) m = fmaxf(m, __shfl_xor_sync(0xFFFFFFFFu, m, off));
    float e = __expf(sc - m);
    float s = e;
#pragma unroll
    for (int off = 16; off; off >>= 1) s += __shfl_xor_sync(0xFFFFFFFFu, s, off);
    const float wat = e / s;

    float4 acc = make_float4(0.f, 0.f, 0.f, 0.f);
#pragma unroll
    for (int kk = 0; kk < 32; kk++) {
        float a = __shfl_sync(0xFFFFFFFFu, wat, kk);
        uint2 v2 = *((const uint2*)&vsh[kk][0] + lane);
        float2 f0 = __half22float2(*(const __half2*)&v2.x);
        float2 f1 = __half22float2(*(const __half2*)&v2.y);
        acc.x += a * f0.x; acc.y += a * f0.y;
        acc.z += a * f1.x; acc.w += a * f1.y;
    }
    __half2 h0 = __floats2half2_rn(acc.x, acc.y);
    __half2 h1 = __floats2half2_rn(acc.z, acc.w);
    uint32_t u0, u1;
    memcpy(&u0, &h0, 4);
    memcpy(&u1, &h1, 4);
    *(uint2*)(y + (size_t)bt * 2048 + g * 512 + w * 128 + lane * 4) =
        make_uint2(u0, u1);
}

// ===================== launch ===============================================
extern "C" void kernel_launch(void* const* d_in, const int* in_sizes, int n_in,
                              void* d_out, int out_size) {
    const float* x    = (const float*)d_in[0];
    const float* cst  = (const float*)d_in[1];
    const int*   mask = (const int*)d_in[2];
    const float* Wq   = (const float*)d_in[3];
    const float* Wk   = (const float*)d_in[4];
    const float* Wv   = (const float*)d_in[5];
    const float* Wo   = (const float*)d_in[6];
    const float* gate = (const float*)d_in[7];
    float* out = (float*)d_out;

    __half *qb, *kb, *vb, *yb, *hx, *hcst, *hwq, *hwk, *hwv, *hwo;
    cudaGetSymbolAddress((void**)&qb, g_q);
    cudaGetSymbolAddress((void**)&yb, g_y);
    cudaGetSymbolAddress((void**)&kb, g_k);
    cudaGetSymbolAddress((void**)&vb, g_v);
    cudaGetSymbolAddress((void**)&hx, g_hx);
    cudaGetSymbolAddress((void**)&hcst, g_hcst);
    cudaGetSymbolAddress((void**)&hwq, g_hwq);
    cudaGetSymbolAddress((void**)&hwk, g_hwk);
    cudaGetSymbolAddress((void**)&hwv, g_hwv);
    cudaGetSymbolAddress((void**)&hwo, g_hwo);

    cudaFuncSetAttribute(fused_gemm1,
                         cudaFuncAttributeMaxDynamicSharedMemorySize, GEMM_SMEM);
    cudaFuncSetAttribute(out_gemm,
                         cudaFuncAttributeMaxDynamicSharedMemorySize, GEMM_SMEM);

    // 0) convert all GEMM inputs to fp16 (one-shot grid, as R9)
    cvt_all<<<15360, 256>>>(x, cst, Wq, Wk, Wv, Wo, hx, hcst, hwq, hwk, hwv, hwo);
    // 1+2) Q + kproj + vproj, all fp16 outputs
    fused_gemm1<<<288, 256, GEMM_SMEM>>>(hx, hcst, hwq, hwk, hwv, qb, kb, vb);
    // 3) gather + tiny-K GQA attention
    attn_kernel<<<dim3(2048, 4), 128>>>(qb, kb, vb, mask, yb);
    // 4) out = (y @ Wo) * tanh(gate)
    out_gemm<<<256, 256, GEMM_SMEM>>>(yb, hwo, out, gate);
}

// round 13
// speedup vs baseline: 1.1143x; 1.0851x over previous
#include <cuda_runtime.h>
#include <cuda_fp16.h>
#include <math.h>
#include <stdint.h>
#include <mma.h>

using namespace nvcuda;

// ===================== static scratch (no allocs allowed) ====================
__device__ __half g_q[2048 * 2048];    // Q projection (fp16)
__device__ __half g_y[2048 * 2048];    // attention out (fp16)
__device__ __half g_k[512 * 512];      // kproj fp16
__device__ __half g_v[512 * 512];      // vproj fp16
__device__ __half g_hx[2048 * 2048];   // x   in fp16
__device__ __half g_hcst[512 * 2048];  // cst in fp16
__device__ __half g_hwq[2048 * 2048];
__device__ __half g_hwk[2048 * 512];
__device__ __half g_hwv[2048 * 512];
__device__ __half g_hwo[2048 * 2048];

__device__ __forceinline__ uint32_t smem_u32(const void* p) {
    uint32_t a;
    asm("{ .reg .u64 t; cvta.to.shared.u64 t, %1; cvt.u32.u64 %0, t; }"
        : "=r"(a) : "l"(p));
    return a;
}
__device__ __forceinline__ void cp_async16(uint32_t dst, const void* src) {
    asm volatile("cp.async.cg.shared.global [%0], [%1], 16;" :: "r"(dst), "l"(src));
}
__device__ __forceinline__ void cp_commit() {
    asm volatile("cp.async.commit_group;" ::: "memory");
}
template <int N>
__device__ __forceinline__ void cp_wait() {
    asm volatile("cp.async.wait_group %0;" :: "n"(N) : "memory");
}

// ===================== fp32 -> fp16 conversion (one-shot, 8B stores) ========
__global__ void __launch_bounds__(256)
cvt_all(const float* __restrict__ x, const float* __restrict__ cst,
        const float* __restrict__ wq, const float* __restrict__ wk,
        const float* __restrict__ wv, const float* __restrict__ wo,
        __half* __restrict__ hx, __half* __restrict__ hcst,
        __half* __restrict__ hwq, __half* __restrict__ hwk,
        __half* __restrict__ hwv, __half* __restrict__ hwo) {
    size_t i = ((size_t)blockIdx.x * blockDim.x + threadIdx.x) * 4;
    const float* src; __half* dst; size_t off;
    if      (i <  4194304u) { src = x;   dst = hx;   off = i; }
    else if (i <  5242880u) { src = cst; dst = hcst; off = i - 4194304u; }
    else if (i <  9437184u) { src = wq;  dst = hwq;  off = i - 5242880u; }
    else if (i < 10485760u) { src = wk;  dst = hwk;  off = i - 9437184u; }
    else if (i < 11534336u) { src = wv;  dst = hwv;  off = i - 10485760u; }
    else if (i < 15728640u) { src = wo;  dst = hwo;  off = i - 11534336u; }
    else return;
    float4 v = *(const float4*)(src + off);
    __half2 h0 = __floats2half2_rn(v.x, v.y);
    __half2 h1 = __floats2half2_rn(v.z, v.w);
    uint32_t u0, u1;
    memcpy(&u0, &h0, 4);
    memcpy(&u1, &h1, 4);
    *(uint2*)(dst + off) = make_uint2(u0, u1);   // single 8B store
}

// ===================== fp16 cp.async GEMM ===================================
// C[M,N] = A[M,K](fp16) @ B[K,N](fp16). BM=BN=128, BK=64, 256 threads
// (8 warps as 4x2, warp tile 32x64), 3-stage cp.async pipeline, 2 CTAs/SM.
// EPI: 1 = fp32 out * tanh(gate), 2 = fp16 out (smem-staged).
constexpr int BK = 64, STAGES = 3;
constexpr int LDA = 72;    // halves (64 + 8 pad) -> 144B pitch
constexpr int LDB = 136;   // halves (128 + 8 pad) -> 272B pitch
constexpr int A_BYTES = 128 * LDA * 2;           // 18432
constexpr int B_BYTES = BK * LDB * 2;            // 17408
constexpr int STAGE_BYTES = A_BYTES + B_BYTES;   // 35840
constexpr int GEMM_SMEM = STAGES * STAGE_BYTES;  // 107520

template <int EPI, typename OutT>
__device__ __forceinline__ void gemm_body(
    const __half* __restrict__ A, const __half* __restrict__ B,
    OutT* __restrict__ C, int N, int K,
    const float* __restrict__ gate, int bx, int by, char* smem) {
    const uint32_t sb = smem_u32(smem);
    const int tid = threadIdx.x;
    const int wid = tid >> 5;
    const int lane = tid & 31;
    const int wm0 = (wid >> 1) * 32;
    const int wn0 = (wid & 1) * 64;
    const int row0 = by * 128;
    const int col0 = bx * 128;
    const int NIT = K / BK;

    const int a_r0 = tid >> 3, a_qb = (tid & 7) * 16;
    const int b_r0 = tid >> 4, b_qb = (tid & 15) * 16;

    auto issue = [&](int it) {
        const int s = it % STAGES;
        const int k0 = it * BK;
        const uint32_t As = sb + s * STAGE_BYTES;
        const uint32_t Bs = As + A_BYTES;
#pragma unroll
        for (int p = 0; p < 4; p++) {
            int r = a_r0 + p * 32;
            cp_async16(As + r * 144 + a_qb,
                       A + (size_t)(row0 + r) * K + k0 + (a_qb >> 1));
        }
#pragma unroll
        for (int p = 0; p < 4; p++) {
            int r = b_r0 + p * 16;
            cp_async16(Bs + r * 272 + b_qb,
                       B + (size_t)(k0 + r) * N + col0 + (b_qb >> 1));
        }
    };

    wmma::fragment<wmma::accumulator, 16, 16, 16, float> acc[2][4];
#pragma unroll
    for (int i = 0; i < 2; i++)
#pragma unroll
        for (int j = 0; j < 4; j++) wmma::fill_fragment(acc[i][j], 0.0f);

#pragma unroll
    for (int s = 0; s < STAGES - 1; s++) {
        issue(s);
        cp_commit();
    }

    for (int it = 0; it < NIT; ++it) {
        cp_wait<STAGES - 2>();
        __syncthreads();

        const int s = it % STAGES;
        const __half* Ah = (const __half*)(smem + s * STAGE_BYTES);
        const __half* Bh = (const __half*)(smem + s * STAGE_BYTES + A_BYTES);

#pragma unroll
        for (int ks = 0; ks < BK / 16; ks++) {
            wmma::fragment<wmma::matrix_a, 16, 16, 16, __half, wmma::row_major> af[2];
            wmma::fragment<wmma::matrix_b, 16, 16, 16, __half, wmma::row_major> bf[4];
#pragma unroll
            for (int i = 0; i < 2; i++)
                wmma::load_matrix_sync(af[i], Ah + (wm0 + i * 16) * LDA + ks * 16, LDA);
#pragma unroll
            for (int j = 0; j < 4; j++)
                wmma::load_matrix_sync(bf[j], Bh + (ks * 16) * LDB + wn0 + j * 16, LDB);
#pragma unroll
            for (int i = 0; i < 2; i++)
#pragma unroll
                for (int j = 0; j < 4; j++)
                    wmma::mma_sync(acc[i][j], af[i], bf[j], acc[i][j]);
        }

        if (it + STAGES - 1 < NIT) issue(it + STAGES - 1);
        cp_commit();
    }

    if (EPI == 2) {
        __syncthreads();
        float* scratch = (float*)smem + wid * 256;
        __half* Ch = (__half*)C;
        const int r = lane >> 1, c8 = (lane & 1) * 8;
#pragma unroll
        for (int i = 0; i < 2; i++)
#pragma unroll
            for (int j = 0; j < 4; j++) {
                wmma::store_matrix_sync(scratch, acc[i][j], 16, wmma::mem_row_major);
                __syncwarp();
                float4 v0 = *(float4*)(scratch + r * 16 + c8);
                float4 v1 = *(float4*)(scratch + r * 16 + c8 + 4);
                __half2 h[4];
                h[0] = __floats2half2_rn(v0.x, v0.y);
                h[1] = __floats2half2_rn(v0.z, v0.w);
                h[2] = __floats2half2_rn(v1.x, v1.y);
                h[3] = __floats2half2_rn(v1.z, v1.w);
                *(uint4*)(Ch + (size_t)(row0 + wm0 + i * 16 + r) * N +
                          col0 + wn0 + j * 16 + c8) = *(uint4*)h;
                __syncwarp();
            }
    } else {
        float g = tanhf(gate[0]);
        float* Cf = (float*)C;
#pragma unroll
        for (int i = 0; i < 2; i++)
#pragma unroll
            for (int j = 0; j < 4; j++) {
#pragma unroll
                for (int e = 0; e < acc[i][j].num_elements; e++)
                    acc[i][j].x[e] *= g;
                wmma::store_matrix_sync(
                    Cf + (size_t)(row0 + wm0 + i * 16) * N + col0 + wn0 + j * 16,
                    acc[i][j], N, wmma::mem_row_major);
            }
    }
}

// stage 1: fused Q(fp16) + kproj(fp16) + vproj(fp16). 288 CTAs, 2/SM.
__global__ void __launch_bounds__(256, 2)
fused_gemm1(const __half* __restrict__ hx, const __half* __restrict__ hcst,
            const __half* __restrict__ hwq, const __half* __restrict__ hwk,
            const __half* __restrict__ hwv, __half* __restrict__ qb,
            __half* __restrict__ kb, __half* __restrict__ vb) {
    extern __shared__ char smem[];
    int bid = blockIdx.x;
    if (bid < 256) {
        gemm_body<2, __half>(hx, hwq, qb, 2048, 2048, nullptr, bid & 15, bid >> 4, smem);
    } else {
        int t = bid - 256;
        int w = t >> 4;
        t &= 15;
        gemm_body<2, __half>(hcst, w ? hwv : hwk, w ? vb : kb, 512, 2048,
                             nullptr, t & 3, t >> 2, smem);
    }
}

// stage 4: out = (y @ Wo) * tanh(gate). 256 CTAs, 2/SM.
__global__ void __launch_bounds__(256, 2)
out_gemm(const __half* __restrict__ y, const __half* __restrict__ hwo,
         float* __restrict__ out, const float* __restrict__ gate) {
    extern __shared__ char smem[];
    gemm_body<1, float>(y, hwo, out, 2048, 2048, gate, blockIdx.x & 15,
                        blockIdx.x >> 4, smem);
}

// ===================== tiny-K attention (R9 version, fp16 smem) =============
__global__ void __launch_bounds__(128)
attn_kernel(const __half* __restrict__ qh, const __half* __restrict__ kh,
            const __half* __restrict__ vh, const int* __restrict__ mask,
            __half* __restrict__ y) {
    __shared__ uint4 qsh[4][17];     // 4 heads x 128 halves (+pad)
    __shared__ uint4 ksh[32][17];    // 32 keys x 128 halves (+pad)
    __shared__ uint4 vsh[32][17];

    const int bt = blockIdx.x;
    const int g  = blockIdx.y;
    const int b  = bt >> 10;
    const int tid  = threadIdx.x;
    const int lane = tid & 31;
    const int w    = tid >> 5;

    const int ch = mask[bt];
    const size_t kvbase = ((size_t)(b * 8 + ch) * 32) * 512 + g * 128;

    if (tid < 64)
        qsh[tid >> 4][tid & 15] =
            *(const uint4*)(qh + (size_t)bt * 2048 + g * 512 + tid * 8);
#pragma unroll
    for (int p = 0; p < 4; p++) {
        int i = tid + p * 128;
        ksh[i >> 4][i & 15] =
            *(const uint4*)(kh + kvbase + (size_t)(i >> 4) * 512 + (i & 15) * 8);
        vsh[i >> 4][i & 15] =
            *(const uint4*)(vh + kvbase + (size_t)(i >> 4) * 512 + (i & 15) * 8);
    }
    __syncthreads();

    float sc = 0.0f;
#pragma unroll
    for (int c = 0; c < 16; c++) {
        uint4 k4 = qsh[w][c];       // broadcast
        uint4 kk4 = ksh[lane][c];
        const __half2* qp = (const __half2*)&k4;
        const __half2* kp = (const __half2*)&kk4;
#pragma unroll
        for (int u = 0; u < 4; u++) {
            float2 qf = __half22float2(qp[u]);
            float2 kf = __half22float2(kp[u]);
            sc += qf.x * kf.x + qf.y * kf.y;
        }
    }
    sc *= 0.08838834764831845f;  // 1/sqrt(128)

    float m = sc;
#pragma unroll
    for (int off = 16; off; off >>= 1) m = fmaxf(m, __shfl_xor_sync(0xFFFFFFFFu, m, off));
    float e = __expf(sc - m);
    float s = e;
#pragma unroll
    for (int off = 16; off; off >>= 1) s += __shfl_xor_sync(0xFFFFFFFFu, s, off);
    const float wat = e / s;

    float4 acc = make_float4(0.f, 0.f, 0.f, 0.f);
#pragma unroll
    for (int kk = 0; kk < 32; kk++) {
        float a = __shfl_sync(0xFFFFFFFFu, wat, kk);
        uint2 v2 = *((const uint2*)&vsh[kk][0] + lane);
        float2 f0 = __half22float2(*(const __half2*)&v2.x);
        float2 f1 = __half22float2(*(const __half2*)&v2.y);
        acc.x += a * f0.x; acc.y += a * f0.y;
        acc.z += a * f1.x; acc.w += a * f1.y;
    }
    __half2 h0 = __floats2half2_rn(acc.x, acc.y);
    __half2 h1 = __floats2half2_rn(acc.z, acc.w);
    uint32_t u0, u1;
    memcpy(&u0, &h0, 4);
    memcpy(&u1, &h1, 4);
    *(uint2*)(y + (size_t)bt * 2048 + g * 512 + w * 128 + lane * 4) =
        make_uint2(u0, u1);
}

// ===================== launch ===============================================
extern "C" void kernel_launch(void* const* d_in, const int* in_sizes, int n_in,
                              void* d_out, int out_size) {
    const float* x    = (const float*)d_in[0];
    const float* cst  = (const float*)d_in[1];
    const int*   mask = (const int*)d_in[2];
    const float* Wq   = (const float*)d_in[3];
    const float* Wk   = (const float*)d_in[4];
    const float* Wv   = (const float*)d_in[5];
    const float* Wo   = (const float*)d_in[6];
    const float* gate = (const float*)d_in[7];
    float* out = (float*)d_out;

    __half *qb, *kb, *vb, *yb, *hx, *hcst, *hwq, *hwk, *hwv, *hwo;
    cudaGetSymbolAddress((void**)&qb, g_q);
    cudaGetSymbolAddress((void**)&yb, g_y);
    cudaGetSymbolAddress((void**)&kb, g_k);
    cudaGetSymbolAddress((void**)&vb, g_v);
    cudaGetSymbolAddress((void**)&hx, g_hx);
    cudaGetSymbolAddress((void**)&hcst, g_hcst);
    cudaGetSymbolAddress((void**)&hwq, g_hwq);
    cudaGetSymbolAddress((void**)&hwk, g_hwk);
    cudaGetSymbolAddress((void**)&hwv, g_hwv);
    cudaGetSymbolAddress((void**)&hwo, g_hwo);

    cudaFuncSetAttribute(fused_gemm1,
                         cudaFuncAttributeMaxDynamicSharedMemorySize, GEMM_SMEM);
    cudaFuncSetAttribute(out_gemm,
                         cudaFuncAttributeMaxDynamicSharedMemorySize, GEMM_SMEM);

    // 0) convert all GEMM inputs to fp16 (one-shot grid, 8B stores)
    cvt_all<<<15360, 256>>>(x, cst, Wq, Wk, Wv, Wo, hx, hcst, hwq, hwk, hwv, hwo);
    // 1+2) Q + kproj + vproj, all fp16 outputs
    fused_gemm1<<<288, 256, GEMM_SMEM>>>(hx, hcst, hwq, hwk, hwv, qb, kb, vb);
    // 3) gather + tiny-K GQA attention
    attn_kernel<<<dim3(2048, 4), 128>>>(qb, kb, vb, mask, yb);
    // 4) out = (y @ Wo) * tanh(gate)
    out_gemm<<<256, 256, GEMM_SMEM>>>(yb, hwo, out, gate);
}